// round 9
// baseline (speedup 1.0000x reference)
#include <cuda_runtime.h>
#include <cuda_pipeline.h>
#include <math.h>
#include <stdint.h>

// ---------------------------------------------------------------------------
// CQT pipeline:
//   fftq : 84 Stockham iFFTs of (kr + i ki) half-spectra -> collapsed
//          time-domain kernels, quantized per-row to 16-bit = 2 s8 limbs.
//   xq   : quantize x (fixed scale 4096) to 2 s8 limbs.
//   s2   : int8 mma.sync GEMM over K=2048:
//          D = 65536*(xh*Ch) + 256*(xh*Cl + xl*Ch)   (ll term dropped)
//   mag  : out[b,f] = sqrt(D_re^2 + D_im^2)
// ---------------------------------------------------------------------------

#define T_SAMPLES 8388608
#define FFTLEN    2048
#define HOP       512
#define NBINS     84
#define KB        1025
#define NFRAMES   16381
#define IM_OFF    96
#define FPAD      16384            // padded frame count in g_D

__device__ int8_t g_x8h[T_SAMPLES];
__device__ int8_t g_x8l[T_SAMPLES];
__device__ int8_t g_b8h[192 * FFTLEN];  // rows 0-95 re, 96-191 im (84 used each)
__device__ int8_t g_b8l[192 * FFTLEN];
__device__ float  g_Sb[192];            // per-row kernel quant scales
__device__ float  g_D[192 * FPAD];      // de-quantized GEMM output

// ---------------- helpers ---------------------------------------------------
__device__ __forceinline__ uint32_t smem_u32(const void* p) {
    uint32_t a;
    asm("{ .reg .u64 t; cvta.to.shared.u64 t, %1; cvt.u32.u64 %0, t; }"
        : "=r"(a) : "l"(p));
    return a;
}
__device__ __forceinline__ void ldmx4(uint32_t* r, uint32_t addr) {
    asm volatile("ldmatrix.sync.aligned.m8n8.x4.shared.b16 {%0,%1,%2,%3}, [%4];"
                 : "=r"(r[0]), "=r"(r[1]), "=r"(r[2]), "=r"(r[3]) : "r"(addr));
}
__device__ __forceinline__ void ldmx2(uint32_t* r, uint32_t addr) {
    asm volatile("ldmatrix.sync.aligned.m8n8.x2.shared.b16 {%0,%1}, [%2];"
                 : "=r"(r[0]), "=r"(r[1]) : "r"(addr));
}
__device__ __forceinline__ void mma_s8(int* d, const uint32_t* a,
                                       uint32_t b0, uint32_t b1) {
    asm volatile(
        "mma.sync.aligned.m16n8k32.row.col.s32.s8.s8.s32 "
        "{%0,%1,%2,%3}, {%4,%5,%6,%7}, {%8,%9}, {%0,%1,%2,%3};"
        : "+r"(d[0]), "+r"(d[1]), "+r"(d[2]), "+r"(d[3])
        : "r"(a[0]), "r"(a[1]), "r"(a[2]), "r"(a[3]), "r"(b0), "r"(b1));
}
#define SW(o) ((o) ^ (((o) >> 3) & 0x70))

__device__ __forceinline__ void split16(int q, int8_t& hi, int8_t& lo) {
    int h = (q + 128) >> 8;                 // round-to-nearest high byte
    hi = (int8_t)h;
    lo = (int8_t)(q - (h << 8));            // in [-128, 127]
}

// ---------------- fftq: collapse bases via iFFT + quantize ------------------
// One block per bin b. C[b][n] = sum_{k<1025} (kr+i ki)[b,k] e^{+i2pi k n/2048}.
__global__ __launch_bounds__(128) void fftq_kernel(
    const float* __restrict__ kr, const float* __restrict__ ki)
{
    __shared__ float2 buf0[FFTLEN], buf1[FFTLEN];
    __shared__ float red[8];
    const int b = blockIdx.x, tid = threadIdx.x;

    for (int k = tid; k < FFTLEN; k += 128) {
        float re = (k < KB) ? kr[b * KB + k] : 0.f;
        float im = (k < KB) ? ki[b * KB + k] : 0.f;
        buf0[k] = make_float2(re, im);
    }
    __syncthreads();

    float2 *src = buf0, *dst = buf1;
    int l = 1, sh = 10;
    for (int s = 0; s < 11; s++) {
        const int m = 1 << sh;
        const float w = 3.14159265358979f / (float)l;
        for (int i = tid; i < 1024; i += 128) {
            int p = i >> sh, q = i & (m - 1);
            float si, co;
            __sincosf(w * (float)p, &si, &co);
            float2 c0 = src[q + ((p << 1)) * m];
            float2 c1 = src[q + ((p << 1) | 1) * m];
            float tr = co * c1.x - si * c1.y;
            float ti = co * c1.y + si * c1.x;
            dst[q + p * m]       = make_float2(c0.x + tr, c0.y + ti);
            dst[q + (p + l) * m] = make_float2(c0.x - tr, c0.y - ti);
        }
        __syncthreads();
        float2* t = src; src = dst; dst = t;
        l <<= 1; sh--;
    }

    // per-row maxabs of re and im parts
    float mre = 0.f, mim = 0.f;
    for (int n = tid; n < FFTLEN; n += 128) {
        mre = fmaxf(mre, fabsf(src[n].x));
        mim = fmaxf(mim, fabsf(src[n].y));
    }
#pragma unroll
    for (int o = 16; o; o >>= 1) {
        mre = fmaxf(mre, __shfl_xor_sync(0xFFFFFFFFu, mre, o));
        mim = fmaxf(mim, __shfl_xor_sync(0xFFFFFFFFu, mim, o));
    }
    if ((tid & 31) == 0) { red[(tid >> 5) * 2] = mre; red[(tid >> 5) * 2 + 1] = mim; }
    __syncthreads();
    mre = fmaxf(fmaxf(red[0], red[2]), fmaxf(red[4], red[6]));
    mim = fmaxf(fmaxf(red[1], red[3]), fmaxf(red[5], red[7]));
    mre = fmaxf(mre, 1e-30f);
    mim = fmaxf(mim, 1e-30f);
    const float ire = 32256.f / mre, iim = 32256.f / mim;

    for (int n = tid; n < FFTLEN; n += 128) {
        int8_t h, lo;
        split16(__float2int_rn(src[n].x * ire), h, lo);
        g_b8h[b * FFTLEN + n] = h;
        g_b8l[b * FFTLEN + n] = lo;
        split16(__float2int_rn(src[n].y * iim), h, lo);
        g_b8h[(IM_OFF + b) * FFTLEN + n] = h;
        g_b8l[(IM_OFF + b) * FFTLEN + n] = lo;
    }
    if (tid == 0) {
        g_Sb[b]          = mre / 32256.f;
        g_Sb[IM_OFF + b] = mim / 32256.f;
    }
}

// ---------------- xq: quantize the signal ----------------------------------
__global__ __launch_bounds__(256) void xq_kernel(const float* __restrict__ x) {
    int i = blockIdx.x * 256 + threadIdx.x;      // 2,097,152 float4 tasks
    float4 v = ((const float4*)x)[i];
    int8_t h[4], l[4];
    int q;
    q = max(min(__float2int_rn(v.x * 4096.f),  32512), -32512); split16(q, h[0], l[0]);
    q = max(min(__float2int_rn(v.y * 4096.f),  32512), -32512); split16(q, h[1], l[1]);
    q = max(min(__float2int_rn(v.z * 4096.f),  32512), -32512); split16(q, h[2], l[2]);
    q = max(min(__float2int_rn(v.w * 4096.f),  32512), -32512); split16(q, h[3], l[3]);
    *(uint32_t*)&g_x8h[i * 4] = *(const uint32_t*)h;
    *(uint32_t*)&g_x8l[i * 4] = *(const uint32_t*)l;
}

// ---------------- s2: int8 GEMM --------------------------------------------
// grid (128 frame-tiles, 2 row-halves), 512 threads, 16 warps (4M x 4N).
// CTA tile: 128 frames x 96 rows. Warp: 32 frames (2 m16) x 24 rows (3 n8).
// K chunks of 128 bytes, 3-stage cp.async ring. Per k32 step all frags are
// loaded once and reused across the 3 limb products.
// Stage SMEM (56 KB): Ah 16K | Al 16K | Bh 12K | Bl 12K.
#define S2_STAGE 57344
#define S2_SMEM  (3 * S2_STAGE)
#define KC8 128
#define NCH (FFTLEN / KC8)          // 16

__global__ __launch_bounds__(512, 1) void s2_int8_kernel() {
    extern __shared__ __align__(1024) char smem[];
    const uint32_t sb = smem_u32(smem);
    const int tid  = threadIdx.x;
    const int wid  = tid >> 5, lane = tid & 31;
    const int wm   = wid & 3,  wn   = wid >> 2;
    const int f0   = blockIdx.x * 128;
    const int nh   = blockIdx.y;                 // 0: re rows, 1: im rows
    const int8_t* __restrict__ srcBh = g_b8h + (size_t)nh * 96 * FFTLEN;
    const int8_t* __restrict__ srcBl = g_b8l + (size_t)nh * 96 * FFTLEN;

    // ldmatrix per-thread address parts (shared swizzle key)
    const uint32_t key  = (lane & 7) << 4;
    const uint32_t off4 = ((lane >> 4) & 1) << 4;      // for x4 loads
    const uint32_t off2 = ((lane >> 3) & 1) << 4;      // for x2 loads
    uint32_t arow[2];
#pragma unroll
    for (int mt = 0; mt < 2; mt++)
        arow[mt] = (uint32_t)(wm * 32 + mt * 16 + ((lane >> 3) & 1) * 8 + (lane & 7)) << 7;
    const uint32_t brow01 = (uint32_t)(wn * 24 + ((lane >> 3) & 1) * 8 + (lane & 7)) << 7;
    const uint32_t brow2  = (uint32_t)(wn * 24 + 16 + (lane & 7)) << 7;

    int acc1[2][3][4], acc2[2][3][4];
#pragma unroll
    for (int mt = 0; mt < 2; mt++)
#pragma unroll
        for (int p = 0; p < 3; p++)
#pragma unroll
            for (int q = 0; q < 4; q++) { acc1[mt][p][q] = 0; acc2[mt][p][q] = 0; }

    auto load_tiles = [&](int stage, int k0) {
        char* st = smem + stage * S2_STAGE;
        // A: 128 frames x 128 B x 2 limbs = 2048 x 16B tasks
        for (int t = tid; t < 2048; t += 512) {
            int limb = t >> 10, rem = t & 1023, m = rem >> 3, ch = rem & 7;
            int f = f0 + m;
            const int8_t* src = (limb ? g_x8l : g_x8h) + (size_t)f * HOP + k0 + ch * 16;
            char* dst = st + limb * 16384 + SW(m * 128 + ch * 16);
            __pipeline_memcpy_async(dst, src, 16, (f < NFRAMES) ? 0u : 16u);
        }
        // B: 96 rows x 128 B x 2 limbs = 1536 x 16B tasks
        for (int t = tid; t < 1536; t += 512) {
            int limb = t / 768, rem = t - limb * 768, r = rem >> 3, ch = rem & 7;
            const int8_t* src = (limb ? srcBl : srcBh) + (size_t)r * FFTLEN + k0 + ch * 16;
            char* dst = st + 32768 + limb * 12288 + SW(r * 128 + ch * 16);
            __pipeline_memcpy_async(dst, src, 16);
        }
    };

    load_tiles(0, 0);            __pipeline_commit();
    load_tiles(1, KC8);          __pipeline_commit();

#pragma unroll 1
    for (int c = 0; c < NCH; c++) {
        if (c + 2 < NCH) { load_tiles((c + 2) % 3, (c + 2) * KC8); __pipeline_commit(); }
        __pipeline_wait_prior(2);
        __syncthreads();

        const uint32_t base = sb + (uint32_t)(c % 3) * S2_STAGE;
        const uint32_t Ah = base, Al = base + 16384;
        const uint32_t Bh = base + 32768, Bl = base + 45056;
#pragma unroll
        for (int ks = 0; ks < 4; ks++) {
            const uint32_t kb = ks * 32;
            const uint32_t o4 = (kb + off4) ^ key;
            const uint32_t o2 = (kb + off2) ^ key;
            uint32_t ah[2][4], al[2][4];
#pragma unroll
            for (int mt = 0; mt < 2; mt++) {
                ldmx4(ah[mt], Ah + arow[mt] + o4);
                ldmx4(al[mt], Al + arow[mt] + o4);
            }
            uint32_t bh01[4], bl01[4], bh2[2], bl2[2];
            ldmx4(bh01, Bh + brow01 + o4);
            ldmx4(bl01, Bl + brow01 + o4);
            ldmx2(bh2,  Bh + brow2  + o2);
            ldmx2(bl2,  Bl + brow2  + o2);
#pragma unroll
            for (int mt = 0; mt < 2; mt++) {
                // p = 0: regs {r0, r2} of the x4 pair; p = 1: {r1, r3}
                mma_s8(acc1[mt][0], ah[mt], bh01[0], bh01[2]);
                mma_s8(acc2[mt][0], ah[mt], bl01[0], bl01[2]);
                mma_s8(acc2[mt][0], al[mt], bh01[0], bh01[2]);
                mma_s8(acc1[mt][1], ah[mt], bh01[1], bh01[3]);
                mma_s8(acc2[mt][1], ah[mt], bl01[1], bl01[3]);
                mma_s8(acc2[mt][1], al[mt], bh01[1], bh01[3]);
                mma_s8(acc1[mt][2], ah[mt], bh2[0],  bh2[1]);
                mma_s8(acc2[mt][2], ah[mt], bl2[0],  bl2[1]);
                mma_s8(acc2[mt][2], al[mt], bh2[0],  bh2[1]);
            }
        }
        __syncthreads();
    }

    // epilogue: de-quantize, write float partials to g_D
    const float SXI = 1.f / 4096.f;
#pragma unroll
    for (int mt = 0; mt < 2; mt++)
#pragma unroll
        for (int p = 0; p < 3; p++)
#pragma unroll
            for (int q = 0; q < 4; q++) {
                int f    = f0 + wm * 32 + mt * 16 + (lane >> 2) + ((q >> 1) << 3);
                int grow = nh * 96 + wn * 24 + 8 * p + ((lane & 3) << 1) + (q & 1);
                float v = (65536.f * (float)acc1[mt][p][q]
                         +   256.f * (float)acc2[mt][p][q]) * g_Sb[grow] * SXI;
                g_D[(size_t)grow * FPAD + f] = v;
            }
}

// ---------------- mag: magnitude epilogue ----------------------------------
__global__ __launch_bounds__(256) void mag_kernel(float* __restrict__ out) {
    const int b = blockIdx.y;
    const int i = blockIdx.x * 256 + threadIdx.x;       // float4 idx, 4096/row
    float4 re = ((const float4*)(g_D + (size_t)b * FPAD))[i];
    float4 im = ((const float4*)(g_D + (size_t)(IM_OFF + b) * FPAD))[i];
    const int f = i * 4;
    float r[4] = {re.x, re.y, re.z, re.w};
    float m[4] = {im.x, im.y, im.z, im.w};
#pragma unroll
    for (int j = 0; j < 4; j++)
        if (f + j < NFRAMES)
            out[(size_t)b * NFRAMES + f + j] = sqrtf(r[j] * r[j] + m[j] * m[j]);
}

// ---------------------------------------------------------------------------
extern "C" void kernel_launch(void* const* d_in, const int* in_sizes, int n_in,
                              void* d_out, int out_size)
{
    const float* x  = (const float*)d_in[0];
    const float* kr = (const float*)d_in[3];
    const float* ki = (const float*)d_in[4];
    float* out = (float*)d_out;

    cudaFuncSetAttribute(s2_int8_kernel,
                         cudaFuncAttributeMaxDynamicSharedMemorySize, S2_SMEM);

    fftq_kernel<<<NBINS, 128>>>(kr, ki);
    xq_kernel<<<T_SAMPLES / 4 / 256, 256>>>(x);
    s2_int8_kernel<<<dim3(128, 2), 512, S2_SMEM>>>();
    mag_kernel<<<dim3(FPAD / 4 / 256, NBINS), 256>>>(out);
}

// round 13
// speedup vs baseline: 1.6431x; 1.6431x over previous
#include <cuda_runtime.h>
#include <cuda_pipeline.h>
#include <cuda_bf16.h>
#include <math.h>
#include <stdint.h>

// ---------------------------------------------------------------------------
// CQT pipeline (bf16 2-limb, mma.sync):
//   fftb  : 84 Stockham iFFTs of (kr + i ki) -> collapsed time-domain kernels
//           C[b][n], written row-interleaved (re_b -> row 2b, im_b -> 2b+1)
//           as bf16 hi/lo limb arrays.
//   xsplit: x -> bf16 hi/lo limb arrays.
//   s2    : mma.sync bf16 GEMM over K=2048, D = Xh*Ch + Xh*Cl + Xl*Ch,
//           fused magnitude epilogue (re/im are adjacent C-frag cols).
// ---------------------------------------------------------------------------

#define T_SAMPLES 8388608
#define FFTLEN    2048
#define HOP       512
#define NBINS     84
#define KB        1025
#define NFRAMES   16381
#define NROWS     192              // 96 interleaved bin pairs (84 used)

__device__ __nv_bfloat16 g_xh[T_SAMPLES];
__device__ __nv_bfloat16 g_xl[T_SAMPLES];
__device__ __nv_bfloat16 g_bh[NROWS * FFTLEN];
__device__ __nv_bfloat16 g_bl[NROWS * FFTLEN];

// ---------------- helpers ---------------------------------------------------
__device__ __forceinline__ uint32_t smem_u32(const void* p) {
    uint32_t a;
    asm("{ .reg .u64 t; cvta.to.shared.u64 t, %1; cvt.u32.u64 %0, t; }"
        : "=r"(a) : "l"(p));
    return a;
}
__device__ __forceinline__ void ldmx4(uint32_t* r, uint32_t addr) {
    asm volatile("ldmatrix.sync.aligned.m8n8.x4.shared.b16 {%0,%1,%2,%3}, [%4];"
                 : "=r"(r[0]), "=r"(r[1]), "=r"(r[2]), "=r"(r[3]) : "r"(addr));
}
__device__ __forceinline__ void mma16816(float* d, const uint32_t* a,
                                         uint32_t b0, uint32_t b1) {
    asm volatile(
        "mma.sync.aligned.m16n8k16.row.col.f32.bf16.bf16.f32 "
        "{%0,%1,%2,%3}, {%4,%5,%6,%7}, {%8,%9}, {%0,%1,%2,%3};"
        : "+f"(d[0]), "+f"(d[1]), "+f"(d[2]), "+f"(d[3])
        : "r"(a[0]), "r"(a[1]), "r"(a[2]), "r"(a[3]), "r"(b0), "r"(b1));
}
#define SW(o) ((o) ^ (((o) >> 3) & 0x70))
__device__ __forceinline__ uint32_t pk(__nv_bfloat16 a, __nv_bfloat16 b) {
    __nv_bfloat162 t(a, b);
    return *(uint32_t*)&t;
}

// ---------------- fftb: collapse bases via iFFT + bf16 limb split ----------
// One block per bin b. C[b][n] = sum_{k<1025} (kr+i ki)[b,k] e^{+i2pi k n/2048}.
__global__ __launch_bounds__(128) void fftb_kernel(
    const float* __restrict__ kr, const float* __restrict__ ki)
{
    __shared__ float2 buf0[FFTLEN], buf1[FFTLEN];
    const int b = blockIdx.x, tid = threadIdx.x;

    for (int k = tid; k < FFTLEN; k += 128) {
        float re = (k < KB) ? kr[b * KB + k] : 0.f;
        float im = (k < KB) ? ki[b * KB + k] : 0.f;
        buf0[k] = make_float2(re, im);
    }
    __syncthreads();

    float2 *src = buf0, *dst = buf1;
    int l = 1, sh = 10;
    for (int s = 0; s < 11; s++) {
        const int m = 1 << sh;
        const float w = 3.14159265358979f / (float)l;
        for (int i = tid; i < 1024; i += 128) {
            int p = i >> sh, q = i & (m - 1);
            float si, co;
            __sincosf(w * (float)p, &si, &co);
            float2 c0 = src[q + ((p << 1)) * m];
            float2 c1 = src[q + ((p << 1) | 1) * m];
            float tr = co * c1.x - si * c1.y;
            float ti = co * c1.y + si * c1.x;
            dst[q + p * m]       = make_float2(c0.x + tr, c0.y + ti);
            dst[q + (p + l) * m] = make_float2(c0.x - tr, c0.y - ti);
        }
        __syncthreads();
        float2* t = src; src = dst; dst = t;
        l <<= 1; sh--;
    }

    // write interleaved bf16 limbs: re -> row 2b, im -> row 2b+1
    for (int n = tid; n < FFTLEN; n += 128) {
        float re = src[n].x, im = src[n].y;
        __nv_bfloat16 hr = __float2bfloat16_rn(re);
        __nv_bfloat16 lr = __float2bfloat16_rn(re - __bfloat162float(hr));
        __nv_bfloat16 hi = __float2bfloat16_rn(im);
        __nv_bfloat16 li = __float2bfloat16_rn(im - __bfloat162float(hi));
        g_bh[(2 * b)     * FFTLEN + n] = hr;
        g_bl[(2 * b)     * FFTLEN + n] = lr;
        g_bh[(2 * b + 1) * FFTLEN + n] = hi;
        g_bl[(2 * b + 1) * FFTLEN + n] = li;
    }
}

// ---------------- xsplit: x -> bf16 hi/lo ----------------------------------
__global__ __launch_bounds__(256) void xsplit_kernel(const float* __restrict__ x) {
    int i = blockIdx.x * 256 + threadIdx.x;       // 2,097,152 float4 tasks
    float4 v = ((const float4*)x)[i];
    __nv_bfloat16 h0 = __float2bfloat16_rn(v.x), h1 = __float2bfloat16_rn(v.y);
    __nv_bfloat16 h2 = __float2bfloat16_rn(v.z), h3 = __float2bfloat16_rn(v.w);
    __nv_bfloat16 l0 = __float2bfloat16_rn(v.x - __bfloat162float(h0));
    __nv_bfloat16 l1 = __float2bfloat16_rn(v.y - __bfloat162float(h1));
    __nv_bfloat16 l2 = __float2bfloat16_rn(v.z - __bfloat162float(h2));
    __nv_bfloat16 l3 = __float2bfloat16_rn(v.w - __bfloat162float(h3));
    ((uint2*)g_xh)[i] = make_uint2(pk(h0, h1), pk(h2, h3));
    ((uint2*)g_xl)[i] = make_uint2(pk(l0, l1), pk(l2, l3));
}

// ---------------- s2: bf16 GEMM + fused magnitude --------------------------
// grid = 128 (one CTA per 128-frame tile, one wave). 512 threads, 16 warps
// (4M x 4N). Warp: 32 frames (2 m16) x 48 rows (6 n8 = 24 bins interleaved).
// K chunks of 64 bf16 (128B rows), double-buffered cp.async. Per k16 step all
// frags loaded once, reused across 3 limb products into the SAME fp32 acc.
// Stage SMEM (80 KB): Ah 16K | Al 16K | Bh 24K | Bl 24K.
#define S2_STAGE 81920
#define S2_SMEM  (2 * S2_STAGE)
#define KC 64
#define NCH (FFTLEN / KC)           // 32

__global__ __launch_bounds__(512, 1) void s2_kernel(float* __restrict__ out) {
    extern __shared__ __align__(1024) char smem[];
    const uint32_t sb = smem_u32(smem);
    const int tid  = threadIdx.x;
    const int wid  = tid >> 5, lane = tid & 31;
    const int wm   = wid & 3,  wn   = wid >> 2;
    const int f0   = blockIdx.x * 128;

    // ldmatrix address components (R6-verified pattern)
    const int i8 = lane & 7, g = lane >> 3;
    const uint32_t key = (uint32_t)i8 << 4;
    uint32_t arow[2];
#pragma unroll
    for (int mt = 0; mt < 2; mt++)
        arow[mt] = (uint32_t)(wm * 32 + mt * 16 + (g & 1) * 8 + i8) << 7;
    const uint32_t acol = (uint32_t)(g >> 1) << 4;
    uint32_t brow[3];
#pragma unroll
    for (int jj = 0; jj < 3; jj++)
        brow[jj] = (uint32_t)(wn * 48 + jj * 16 + ((g >> 1) & 1) * 8 + i8) << 7;
    const uint32_t bcol = (uint32_t)(g & 1) << 4;

    float acc[2][6][4];
#pragma unroll
    for (int mt = 0; mt < 2; mt++)
#pragma unroll
        for (int n = 0; n < 6; n++)
#pragma unroll
            for (int q = 0; q < 4; q++) acc[mt][n][q] = 0.f;

    auto load_tiles = [&](int stage, int k0) {
        char* st = smem + stage * S2_STAGE;
        // A: 2 limbs x 128 frame-rows x 8 chunks of 16B = 2048 tasks
        for (int t = tid; t < 2048; t += 512) {
            int limb = t >> 10, rem = t & 1023, m = rem >> 3, ch = rem & 7;
            int f = f0 + m;
            const __nv_bfloat16* src =
                (limb ? g_xl : g_xh) + (size_t)f * HOP + k0 + ch * 8;
            char* dst = st + limb * 16384 + SW(m * 128 + ch * 16);
            __pipeline_memcpy_async(dst, src, 16, (f < NFRAMES) ? 0u : 16u);
        }
        // B: 2 limbs x 192 rows x 8 chunks = 3072 tasks
        for (int t = tid; t < 3072; t += 512) {
            int limb = t >> 10;          // 0,0?,.. careful: 3072 = 2*1536
            int arr  = t / 1536, rem = t - arr * 1536;
            int r = rem >> 3, ch = rem & 7;
            const __nv_bfloat16* src =
                (arr ? g_bl : g_bh) + (size_t)r * FFTLEN + k0 + ch * 8;
            char* dst = st + 32768 + arr * 24576 + SW(r * 128 + ch * 16);
            __pipeline_memcpy_async(dst, src, 16);
            (void)limb;
        }
    };

    load_tiles(0, 0);
    __pipeline_commit();

#pragma unroll 1
    for (int c = 0; c < NCH; c++) {
        const int buf = c & 1;
        if (c + 1 < NCH) {
            load_tiles(buf ^ 1, (c + 1) * KC);
            __pipeline_commit();
            __pipeline_wait_prior(1);
        } else {
            __pipeline_wait_prior(0);
        }
        __syncthreads();

        const uint32_t base = sb + (uint32_t)buf * S2_STAGE;
        const uint32_t Ah = base, Al = base + 16384;
        const uint32_t Bh = base + 32768, Bl = base + 57344;
#pragma unroll
        for (int ks = 0; ks < 4; ks++) {
            const uint32_t kb = ks * 32;
            const uint32_t oa = (kb + acol) ^ key;
            const uint32_t ob = (kb + bcol) ^ key;
            uint32_t ah[2][4], al[2][4], bh[3][4], bl[3][4];
#pragma unroll
            for (int mt = 0; mt < 2; mt++) {
                ldmx4(ah[mt], Ah + arow[mt] + oa);
                ldmx4(al[mt], Al + arow[mt] + oa);
            }
#pragma unroll
            for (int jj = 0; jj < 3; jj++) {
                ldmx4(bh[jj], Bh + brow[jj] + ob);
                ldmx4(bl[jj], Bl + brow[jj] + ob);
            }
            // pass 1: Ah*Bh   (acc targets rotate: 12 independent per pass)
#pragma unroll
            for (int mt = 0; mt < 2; mt++)
#pragma unroll
                for (int jj = 0; jj < 3; jj++) {
                    mma16816(acc[mt][2 * jj],     ah[mt], bh[jj][0], bh[jj][1]);
                    mma16816(acc[mt][2 * jj + 1], ah[mt], bh[jj][2], bh[jj][3]);
                }
            // pass 2: Ah*Bl
#pragma unroll
            for (int mt = 0; mt < 2; mt++)
#pragma unroll
                for (int jj = 0; jj < 3; jj++) {
                    mma16816(acc[mt][2 * jj],     ah[mt], bl[jj][0], bl[jj][1]);
                    mma16816(acc[mt][2 * jj + 1], ah[mt], bl[jj][2], bl[jj][3]);
                }
            // pass 3: Al*Bh
#pragma unroll
            for (int mt = 0; mt < 2; mt++)
#pragma unroll
                for (int jj = 0; jj < 3; jj++) {
                    mma16816(acc[mt][2 * jj],     al[mt], bh[jj][0], bh[jj][1]);
                    mma16816(acc[mt][2 * jj + 1], al[mt], bh[jj][2], bh[jj][3]);
                }
        }
        __syncthreads();
    }

    // fused magnitude epilogue: d0,d1 = (re,im) of one bin (interleaved rows)
#pragma unroll
    for (int mt = 0; mt < 2; mt++)
#pragma unroll
        for (int n = 0; n < 6; n++) {
            int bin = wn * 24 + n * 4 + (lane & 3);
            int f   = f0 + wm * 32 + mt * 16 + (lane >> 2);
            if (bin < NBINS) {
                if (f < NFRAMES)
                    out[(size_t)bin * NFRAMES + f] =
                        sqrtf(acc[mt][n][0] * acc[mt][n][0] +
                              acc[mt][n][1] * acc[mt][n][1]);
                if (f + 8 < NFRAMES)
                    out[(size_t)bin * NFRAMES + f + 8] =
                        sqrtf(acc[mt][n][2] * acc[mt][n][2] +
                              acc[mt][n][3] * acc[mt][n][3]);
            }
        }
}

// ---------------------------------------------------------------------------
extern "C" void kernel_launch(void* const* d_in, const int* in_sizes, int n_in,
                              void* d_out, int out_size)
{
    const float* x  = (const float*)d_in[0];
    const float* kr = (const float*)d_in[3];
    const float* ki = (const float*)d_in[4];
    float* out = (float*)d_out;

    cudaFuncSetAttribute(s2_kernel,
                         cudaFuncAttributeMaxDynamicSharedMemorySize, S2_SMEM);

    fftb_kernel<<<NBINS, 128>>>(kr, ki);
    xsplit_kernel<<<T_SAMPLES / 4 / 256, 256>>>(x);
    s2_kernel<<<128, 512, S2_SMEM>>>(out);
}

// round 17
// speedup vs baseline: 2.5849x; 1.5732x over previous
#include <cuda_runtime.h>
#include <cuda_pipeline.h>
#include <cuda_bf16.h>
#include <math.h>
#include <stdint.h>

// ---------------------------------------------------------------------------
// CQT pipeline (bf16 2-limb, mma.sync):
//   fftb  : 84 Stockham iFFTs of (kr + i ki) -> collapsed time-domain kernels
//           C[b][n], row-interleaved (re_b -> row 2b, im_b -> 2b+1), bf16
//           hi/lo limbs.
//   xsplit: x -> bf16 hi/lo limbs.
//   s2    : mma.sync bf16 GEMM over K=2048, D = Xh*Ch + Xh*Cl + Xl*Ch,
//           fused magnitude epilogue (re/im adjacent in the C fragment).
// ---------------------------------------------------------------------------

#define T_SAMPLES 8388608
#define FFTLEN    2048
#define HOP       512
#define NBINS     84
#define KB        1025
#define NFRAMES   16381
#define NROWS     192

__device__ __nv_bfloat16 g_xh[T_SAMPLES];
__device__ __nv_bfloat16 g_xl[T_SAMPLES];
__device__ __nv_bfloat16 g_bh[NROWS * FFTLEN];
__device__ __nv_bfloat16 g_bl[NROWS * FFTLEN];

// ---------------- helpers ---------------------------------------------------
__device__ __forceinline__ uint32_t smem_u32(const void* p) {
    uint32_t a;
    asm("{ .reg .u64 t; cvta.to.shared.u64 t, %1; cvt.u32.u64 %0, t; }"
        : "=r"(a) : "l"(p));
    return a;
}
__device__ __forceinline__ void ldmx4(uint32_t* r, uint32_t addr) {
    asm volatile("ldmatrix.sync.aligned.m8n8.x4.shared.b16 {%0,%1,%2,%3}, [%4];"
                 : "=r"(r[0]), "=r"(r[1]), "=r"(r[2]), "=r"(r[3]) : "r"(addr));
}
__device__ __forceinline__ void mma16816(float* d, const uint32_t* a,
                                         uint32_t b0, uint32_t b1) {
    asm volatile(
        "mma.sync.aligned.m16n8k16.row.col.f32.bf16.bf16.f32 "
        "{%0,%1,%2,%3}, {%4,%5,%6,%7}, {%8,%9}, {%0,%1,%2,%3};"
        : "+f"(d[0]), "+f"(d[1]), "+f"(d[2]), "+f"(d[3])
        : "r"(a[0]), "r"(a[1]), "r"(a[2]), "r"(a[3]), "r"(b0), "r"(b1));
}
#define SW(o) ((o) ^ (((o) >> 3) & 0x70))
__device__ __forceinline__ uint32_t pk(__nv_bfloat16 a, __nv_bfloat16 b) {
    __nv_bfloat162 t(a, b);
    return *(uint32_t*)&t;
}

// ---------------- fftb: collapse bases via iFFT + bf16 limb split ----------
// One block per bin b, 256 threads.
__global__ __launch_bounds__(256) void fftb_kernel(
    const float* __restrict__ kr, const float* __restrict__ ki)
{
    __shared__ float2 buf0[FFTLEN], buf1[FFTLEN];
    const int b = blockIdx.x, tid = threadIdx.x;

    for (int k = tid; k < FFTLEN; k += 256) {
        float re = (k < KB) ? kr[b * KB + k] : 0.f;
        float im = (k < KB) ? ki[b * KB + k] : 0.f;
        buf0[k] = make_float2(re, im);
    }
    __syncthreads();

    float2 *src = buf0, *dst = buf1;
    int l = 1, sh = 10;
    for (int s = 0; s < 11; s++) {
        const int m = 1 << sh;
        const float w = 3.14159265358979f / (float)l;
        for (int i = tid; i < 1024; i += 256) {
            int p = i >> sh, q = i & (m - 1);
            float si, co;
            __sincosf(w * (float)p, &si, &co);
            float2 c0 = src[q + ((p << 1)) * m];
            float2 c1 = src[q + ((p << 1) | 1) * m];
            float tr = co * c1.x - si * c1.y;
            float ti = co * c1.y + si * c1.x;
            dst[q + p * m]       = make_float2(c0.x + tr, c0.y + ti);
            dst[q + (p + l) * m] = make_float2(c0.x - tr, c0.y - ti);
        }
        __syncthreads();
        float2* t = src; src = dst; dst = t;
        l <<= 1; sh--;
    }

    for (int n = tid; n < FFTLEN; n += 256) {
        float re = src[n].x, im = src[n].y;
        __nv_bfloat16 hr = __float2bfloat16_rn(re);
        __nv_bfloat16 lr = __float2bfloat16_rn(re - __bfloat162float(hr));
        __nv_bfloat16 hi = __float2bfloat16_rn(im);
        __nv_bfloat16 li = __float2bfloat16_rn(im - __bfloat162float(hi));
        g_bh[(2 * b)     * FFTLEN + n] = hr;
        g_bl[(2 * b)     * FFTLEN + n] = lr;
        g_bh[(2 * b + 1) * FFTLEN + n] = hi;
        g_bl[(2 * b + 1) * FFTLEN + n] = li;
    }
}

// ---------------- xsplit: x -> bf16 hi/lo ----------------------------------
__global__ __launch_bounds__(256) void xsplit_kernel(const float* __restrict__ x) {
    int i = blockIdx.x * 256 + threadIdx.x;       // 2,097,152 float4 tasks
    float4 v = ((const float4*)x)[i];
    __nv_bfloat16 h0 = __float2bfloat16_rn(v.x), h1 = __float2bfloat16_rn(v.y);
    __nv_bfloat16 h2 = __float2bfloat16_rn(v.z), h3 = __float2bfloat16_rn(v.w);
    __nv_bfloat16 l0 = __float2bfloat16_rn(v.x - __bfloat162float(h0));
    __nv_bfloat16 l1 = __float2bfloat16_rn(v.y - __bfloat162float(h1));
    __nv_bfloat16 l2 = __float2bfloat16_rn(v.z - __bfloat162float(h2));
    __nv_bfloat16 l3 = __float2bfloat16_rn(v.w - __bfloat162float(h3));
    ((uint2*)g_xh)[i] = make_uint2(pk(h0, h1), pk(h2, h3));
    ((uint2*)g_xl)[i] = make_uint2(pk(l0, l1), pk(l2, l3));
}

// ---------------- s2: bf16 GEMM + fused magnitude --------------------------
// grid = 128 (one CTA per 128-frame tile, one wave). 512 threads, 16 warps
// (4M x 4N). Warp: 32 frames x 48 rows (24 interleaved bins). K chunks of 64
// bf16, double-buffered cp.async. Inner loop loads B frags per-jj to keep
// live registers under the 128/thread cap (R13 spilled here).
#define S2_STAGE 81920
#define S2_SMEM  (2 * S2_STAGE)
#define KC 64
#define NCH (FFTLEN / KC)           // 32

__global__ __launch_bounds__(512, 1) void s2_kernel(float* __restrict__ out) {
    extern __shared__ __align__(1024) char smem[];
    const uint32_t sb = smem_u32(smem);
    const int tid  = threadIdx.x;
    const int wid  = tid >> 5, lane = tid & 31;
    const int wm   = wid & 3,  wn   = wid >> 2;
    const int f0   = blockIdx.x * 128;

    const int i8 = lane & 7, g = lane >> 3;
    const uint32_t key = (uint32_t)i8 << 4;
    uint32_t arow[2];
#pragma unroll
    for (int mt = 0; mt < 2; mt++)
        arow[mt] = (uint32_t)(wm * 32 + mt * 16 + (g & 1) * 8 + i8) << 7;
    const uint32_t acol = (uint32_t)(g >> 1) << 4;
    uint32_t brow[3];
#pragma unroll
    for (int jj = 0; jj < 3; jj++)
        brow[jj] = (uint32_t)(wn * 48 + jj * 16 + ((g >> 1) & 1) * 8 + i8) << 7;
    const uint32_t bcol = (uint32_t)(g & 1) << 4;

    float acc[2][6][4];
#pragma unroll
    for (int mt = 0; mt < 2; mt++)
#pragma unroll
        for (int n = 0; n < 6; n++)
#pragma unroll
            for (int q = 0; q < 4; q++) acc[mt][n][q] = 0.f;

    auto load_tiles = [&](int stage, int k0) {
        char* st = smem + stage * S2_STAGE;
        // A: 2 limbs x 128 frame-rows x 8 chunks of 16B = 2048 tasks
        for (int t = tid; t < 2048; t += 512) {
            int limb = t >> 10, rem = t & 1023, m = rem >> 3, ch = rem & 7;
            int f = f0 + m;
            const __nv_bfloat16* src =
                (limb ? g_xl : g_xh) + (size_t)f * HOP + k0 + ch * 8;
            char* dst = st + limb * 16384 + SW(m * 128 + ch * 16);
            __pipeline_memcpy_async(dst, src, 16, (f < NFRAMES) ? 0u : 16u);
        }
        // B: 2 limbs x 192 rows x 8 chunks = 3072 tasks
        for (int t = tid; t < 3072; t += 512) {
            int arr = t / 1536, rem = t - arr * 1536;
            int r = rem >> 3, ch = rem & 7;
            const __nv_bfloat16* src =
                (arr ? g_bl : g_bh) + (size_t)r * FFTLEN + k0 + ch * 8;
            char* dst = st + 32768 + arr * 24576 + SW(r * 128 + ch * 16);
            __pipeline_memcpy_async(dst, src, 16);
        }
    };

    load_tiles(0, 0);
    __pipeline_commit();

#pragma unroll 1
    for (int c = 0; c < NCH; c++) {
        const int buf = c & 1;
        if (c + 1 < NCH) {
            load_tiles(buf ^ 1, (c + 1) * KC);
            __pipeline_commit();
            __pipeline_wait_prior(1);
        } else {
            __pipeline_wait_prior(0);
        }
        __syncthreads();

        const uint32_t base = sb + (uint32_t)buf * S2_STAGE;
        const uint32_t Ah = base, Al = base + 16384;
        const uint32_t Bh = base + 32768, Bl = base + 57344;
#pragma unroll
        for (int ks = 0; ks < 4; ks++) {
            const uint32_t kb = ks * 32;
            const uint32_t oa = (kb + acol) ^ key;
            const uint32_t ob = (kb + bcol) ^ key;
            uint32_t ah[2][4], al[2][4];
#pragma unroll
            for (int mt = 0; mt < 2; mt++) {
                ldmx4(ah[mt], Ah + arow[mt] + oa);
                ldmx4(al[mt], Al + arow[mt] + oa);
            }
#pragma unroll
            for (int jj = 0; jj < 3; jj++) {
                uint32_t bh[4], bl[4];
                ldmx4(bh, Bh + brow[jj] + ob);
                ldmx4(bl, Bl + brow[jj] + ob);
#pragma unroll
                for (int mt = 0; mt < 2; mt++) {
                    mma16816(acc[mt][2 * jj],     ah[mt], bh[0], bh[1]);
                    mma16816(acc[mt][2 * jj + 1], ah[mt], bh[2], bh[3]);
                    mma16816(acc[mt][2 * jj],     ah[mt], bl[0], bl[1]);
                    mma16816(acc[mt][2 * jj + 1], ah[mt], bl[2], bl[3]);
                    mma16816(acc[mt][2 * jj],     al[mt], bh[0], bh[1]);
                    mma16816(acc[mt][2 * jj + 1], al[mt], bh[2], bh[3]);
                }
            }
        }
        __syncthreads();
    }

    // fused magnitude epilogue: d0,d1 = (re,im) of one bin (interleaved rows)
#pragma unroll
    for (int mt = 0; mt < 2; mt++)
#pragma unroll
        for (int n = 0; n < 6; n++) {
            int bin = wn * 24 + n * 4 + (lane & 3);
            int f   = f0 + wm * 32 + mt * 16 + (lane >> 2);
            if (bin < NBINS) {
                if (f < NFRAMES)
                    out[(size_t)bin * NFRAMES + f] =
                        sqrtf(acc[mt][n][0] * acc[mt][n][0] +
                              acc[mt][n][1] * acc[mt][n][1]);
                if (f + 8 < NFRAMES)
                    out[(size_t)bin * NFRAMES + f + 8] =
                        sqrtf(acc[mt][n][2] * acc[mt][n][2] +
                              acc[mt][n][3] * acc[mt][n][3]);
            }
        }
}

// ---------------------------------------------------------------------------
extern "C" void kernel_launch(void* const* d_in, const int* in_sizes, int n_in,
                              void* d_out, int out_size)
{
    const float* x  = (const float*)d_in[0];
    const float* kr = (const float*)d_in[3];
    const float* ki = (const float*)d_in[4];
    float* out = (float*)d_out;

    cudaFuncSetAttribute(s2_kernel,
                         cudaFuncAttributeMaxDynamicSharedMemorySize, S2_SMEM);

    fftb_kernel<<<NBINS, 256>>>(kr, ki);
    xsplit_kernel<<<T_SAMPLES / 4 / 256, 256>>>(x);
    s2_kernel<<<128, 512, S2_SMEM>>>(out);
}